// round 8
// baseline (speedup 1.0000x reference)
#include <cuda_runtime.h>
#include <cuda_fp16.h>

#define NN    30000
#define DD    32
#define HH    128
#define KD    10
#define AP    144      // A row pitch (floats) == padded K
#define KTOT  144      // 128 n1h + 2 x + 10 label + 1 S + 3 zero-pad
#define NPAD  30080    // 235 * 128

#define BS_SMEM (KTOT * HH * 4)   // 73728 B -> 2 CTAs/SM

typedef unsigned long long ull;

__device__ __forceinline__ ull pack2(float a, float b) {
    ull r; asm("mov.b64 %0, {%1, %2};" : "=l"(r) : "f"(a), "f"(b)); return r;
}
__device__ __forceinline__ ull fma2(ull a, ull b, ull c) {
    ull d; asm("fma.rn.f32x2 %0, %1, %2, %3;" : "=l"(d) : "l"(a), "l"(b), "l"(c)); return d;
}
__device__ __forceinline__ float2 unpk(ull v) {
    float2 r; asm("mov.b64 {%0, %1}, %2;" : "=f"(r.x), "=f"(r.y) : "l"(v)); return r;
}

__device__ float  g_B[KTOT * HH];       // assembled B matrix [144][128]
__device__ float  g_bsum[HH];           // b0 + b1 + b2
__device__ __half g_feat[NN * HH];      // fp16 feature cache (7.68 MB, L2-resident)
__device__ float  g_A[NPAD * AP];       // augmented A; cols 141-143 & rows>=NN stay 0

// ------------------------------------------------- prep: build g_B + g_bsum
__global__ void prep_kernel(const float* __restrict__ W0, const float* __restrict__ b0,
                            const float* __restrict__ W1, const float* __restrict__ b1,
                            const float* __restrict__ W2, const float* __restrict__ b2,
                            const float* __restrict__ Wt3, const float* __restrict__ Wt4) {
    int r = blockIdx.x, j = threadIdx.x;
    float v = 0.f;
    if (r < 128)                 v = W2[r * HH + j];
    else if (r < 130)            v = W0[(r - 128) * HH + j];
    else if (r < 140)            v = W1[(r - 130) * HH + j];
    else if (r == 140) {         // c = relu(Wt4) @ Wt3
        float acc = 0.f;
#pragma unroll 8
        for (int h = 0; h < HH; ++h) {
            float t = Wt4[h];
            t = t > 0.f ? t : 0.f;
            acc += t * Wt3[h * HH + j];
        }
        v = acc;
    }                            // rows 141-143: 0
    g_B[r * HH + j] = v;
    if (r == 0) g_bsum[j] = b0[j] + b1[j] + b2[j];
}

// ------------------------------------------------- fp32 -> fp16 feature
__global__ void convert_kernel(const float* __restrict__ f) {
    int i = blockIdx.x * 256 + threadIdx.x;        // one float4 per thread
    float4 v = ((const float4*)f)[i];
    __half2 h0 = __float22half2_rn(make_float2(v.x, v.y));
    __half2 h1 = __float22half2_rn(make_float2(v.z, v.w));
    uint2 o;
    o.x = *(unsigned*)&h0;
    o.y = *(unsigned*)&h1;
    ((uint2*)g_feat)[i] = o;
}

// ------------------------------------------------- gather: 1 warp / node
__global__ void __launch_bounds__(256, 3)
gather_kernel(const float* __restrict__ x,  const float* __restrict__ label,
              const float* __restrict__ w,  const float* __restrict__ et,
              const int*   __restrict__ src) {
    __shared__ float2 meta[8][DD];
    const int wp = threadIdx.x >> 5, lane = threadIdx.x & 31;
    const int n  = blockIdx.x * 8 + wp;            // 3750 * 8 == 30000

    const int base = n * DD + lane;
    int   s_l = src[base];
    float e_l = ((const float2*)et)[base].x;       // et[...,0]
    float S   = w[base] * e_l;
#pragma unroll
    for (int o = 16; o; o >>= 1) S += __shfl_xor_sync(0xffffffffu, S, o);
    meta[wp][lane] = make_float2(e_l, __int_as_float(s_l));
    __syncwarp();

    const uint2* fp = (const uint2*)g_feat;        // 32 uint2 per row (256B)
    float2 a0 = make_float2(0.f, 0.f), a1 = make_float2(0.f, 0.f);
#pragma unroll
    for (int d = 0; d < DD; ++d) {
        float2 me = meta[wp][d];
        int   s = __float_as_int(me.y);
        float e = me.x;
        uint2 q = __ldg(fp + s * (HH / 4) + lane);
        float2 f0 = __half22float2(*(__half2*)&q.x);
        float2 f1 = __half22float2(*(__half2*)&q.y);
        a0.x += f0.x * e; a0.y += f0.y * e;
        a1.x += f1.x * e; a1.y += f1.y * e;
    }

    float* Ar = g_A + n * AP;
    ((float4*)Ar)[lane] = make_float4(a0.x, a0.y, a1.x, a1.y);
    if (lane == 0) Ar[140] = S;
    if (lane < 2)  Ar[128 + lane] = x[n * 2 + lane];
    if (lane < KD) Ar[130 + lane] = label[n * KD + lane];
}

// ------------------------------------------------- GEMM: relu(A[128xK] @ B[Kx128] + bsum)
// 256 threads, thread tile 8m x 8j. B: full-K smem. A: direct LDG.128 (L1-streamed).
__global__ void __launch_bounds__(256, 2)
gemm_kernel(float* __restrict__ out) {
    extern __shared__ float Bs[];       // [144][128]

    const int tid = threadIdx.x;
    const int jb  = (tid & 15) * 8;
    const int mb  = (tid >> 4) * 8;
    const int n0  = blockIdx.x * 128;

    // stage B: 4608 float4, 18 per thread
#pragma unroll
    for (int t = 0; t < 18; ++t) {
        int i = t * 256 + tid;
        ((float4*)Bs)[i] = __ldg((const float4*)g_B + i);
    }

    ull acc[8][4];
    {
        union { float4 f; ull v[2]; } i0, i1;
        i0.f = __ldg((const float4*)(g_bsum + jb));
        i1.f = __ldg((const float4*)(g_bsum + jb + 4));
#pragma unroll
        for (int i = 0; i < 8; ++i) {
            acc[i][0] = i0.v[0]; acc[i][1] = i0.v[1];
            acc[i][2] = i1.v[0]; acc[i][3] = i1.v[1];
        }
    }
    __syncthreads();

    const float* Ab = g_A + (size_t)(n0 + mb) * AP;

    for (int kg = 0; kg < KTOT / 4; ++kg) {
        const int k0 = kg * 4;
        // batch-load 8 B vectors for k0..k0+3 (amortize LDS latency over 128 FFMA2)
        union { float4 f; ull v[2]; } bv[8];
#pragma unroll
        for (int kk = 0; kk < 4; ++kk) {
            bv[2 * kk].f     = *(const float4*)(Bs + (k0 + kk) * HH + jb);
            bv[2 * kk + 1].f = *(const float4*)(Bs + (k0 + kk) * HH + jb + 4);
        }
#pragma unroll
        for (int m = 0; m < 8; ++m) {
            float4 av = __ldg((const float4*)(Ab + m * AP + k0));  // 4 A values (k0..k0+3)
            ull a0 = pack2(av.x, av.x);
            ull a1 = pack2(av.y, av.y);
            ull a2 = pack2(av.z, av.z);
            ull a3 = pack2(av.w, av.w);
            acc[m][0] = fma2(a0, bv[0].v[0], acc[m][0]);
            acc[m][1] = fma2(a0, bv[0].v[1], acc[m][1]);
            acc[m][2] = fma2(a0, bv[1].v[0], acc[m][2]);
            acc[m][3] = fma2(a0, bv[1].v[1], acc[m][3]);
            acc[m][0] = fma2(a1, bv[2].v[0], acc[m][0]);
            acc[m][1] = fma2(a1, bv[2].v[1], acc[m][1]);
            acc[m][2] = fma2(a1, bv[3].v[0], acc[m][2]);
            acc[m][3] = fma2(a1, bv[3].v[1], acc[m][3]);
            acc[m][0] = fma2(a2, bv[4].v[0], acc[m][0]);
            acc[m][1] = fma2(a2, bv[4].v[1], acc[m][1]);
            acc[m][2] = fma2(a2, bv[5].v[0], acc[m][2]);
            acc[m][3] = fma2(a2, bv[5].v[1], acc[m][3]);
            acc[m][0] = fma2(a3, bv[6].v[0], acc[m][0]);
            acc[m][1] = fma2(a3, bv[6].v[1], acc[m][1]);
            acc[m][2] = fma2(a3, bv[7].v[0], acc[m][2]);
            acc[m][3] = fma2(a3, bv[7].v[1], acc[m][3]);
        }
    }

#pragma unroll
    for (int i = 0; i < 8; ++i) {
        int n = n0 + mb + i;
        if (n < NN) {
            float2 q0 = unpk(acc[i][0]), q1 = unpk(acc[i][1]);
            float2 q2 = unpk(acc[i][2]), q3 = unpk(acc[i][3]);
            float4 r0, r1;
            r0.x = fmaxf(q0.x, 0.f); r0.y = fmaxf(q0.y, 0.f);
            r0.z = fmaxf(q1.x, 0.f); r0.w = fmaxf(q1.y, 0.f);
            r1.x = fmaxf(q2.x, 0.f); r1.y = fmaxf(q2.y, 0.f);
            r1.z = fmaxf(q3.x, 0.f); r1.w = fmaxf(q3.y, 0.f);
            ((float4*)(out + n * HH + jb))[0] = r0;
            ((float4*)(out + n * HH + jb))[1] = r1;
        }
    }
}

// ------------------------------------------------- launch
extern "C" void kernel_launch(void* const* d_in, const int* in_sizes, int n_in,
                              void* d_out, int out_size) {
    const float* feature = (const float*)d_in[0];
    const float* x       = (const float*)d_in[1];
    const float* label   = (const float*)d_in[2];
    const float* w       = (const float*)d_in[3];
    const float* et      = (const float*)d_in[4];
    const int*   src     = (const int*)  d_in[5];
    const float* W0      = (const float*)d_in[6];
    const float* b0      = (const float*)d_in[7];
    const float* W1      = (const float*)d_in[8];
    const float* b1      = (const float*)d_in[9];
    const float* W2      = (const float*)d_in[10];
    const float* b2      = (const float*)d_in[11];
    const float* Wt3     = (const float*)d_in[12];
    const float* Wt4     = (const float*)d_in[13];
    float* out = (float*)d_out;

    cudaFuncSetAttribute(gemm_kernel, cudaFuncAttributeMaxDynamicSharedMemorySize,
                         BS_SMEM);

    prep_kernel<<<KTOT, HH>>>(W0, b0, W1, b1, W2, b2, Wt3, Wt4);
    convert_kernel<<<(NN * HH / 4) / 256, 256>>>(feature);     // 3750 blocks
    gather_kernel<<<NN / 8, 256>>>(x, label, w, et, src);      // 3750 blocks
    gemm_kernel<<<NPAD / 128, 256, BS_SMEM>>>(out);            // 235 blocks
}

// round 9
// speedup vs baseline: 1.2826x; 1.2826x over previous
#include <cuda_runtime.h>
#include <cuda_fp16.h>

#define NN    30000
#define DD    32
#define HH    128
#define KD    10
#define AP    144      // A row pitch (floats) == padded K
#define KTOT  144      // 128 n1h + 2 x + 10 label + 1 S + 3 zero-pad
#define KC    48       // K chunk
#define NPAD  30080    // 235 * 128
#define ASP   52       // As smem row pitch: %4==0 for LDS.128, pad vs 48

#define GEMM_SMEM ((128 * ASP + KC * HH) * 4)   // 51200 B -> 2 CTAs/SM

typedef unsigned long long ull;

__device__ __forceinline__ ull pack2(float a, float b) {
    ull r; asm("mov.b64 %0, {%1, %2};" : "=l"(r) : "f"(a), "f"(b)); return r;
}
__device__ __forceinline__ ull fma2(ull a, ull b, ull c) {
    ull d; asm("fma.rn.f32x2 %0, %1, %2, %3;" : "=l"(d) : "l"(a), "l"(b), "l"(c)); return d;
}
__device__ __forceinline__ float2 unpk(ull v) {
    float2 r; asm("mov.b64 {%0, %1}, %2;" : "=f"(r.x), "=f"(r.y) : "l"(v)); return r;
}

__device__ float  g_B[KTOT * HH];       // assembled B matrix [144][128]
__device__ float  g_bsum[HH];           // b0 + b1 + b2
__device__ __half g_feat[NN * HH];      // fp16 feature cache (7.68 MB, L2-resident)
__device__ float  g_A[NPAD * AP];       // augmented A; cols 141-143 & rows>=NN stay 0

// ------------------------------------------------- prep: build g_B + g_bsum
__global__ void prep_kernel(const float* __restrict__ W0, const float* __restrict__ b0,
                            const float* __restrict__ W1, const float* __restrict__ b1,
                            const float* __restrict__ W2, const float* __restrict__ b2,
                            const float* __restrict__ Wt3, const float* __restrict__ Wt4) {
    int r = blockIdx.x, j = threadIdx.x;
    float v = 0.f;
    if (r < 128)                 v = W2[r * HH + j];
    else if (r < 130)            v = W0[(r - 128) * HH + j];
    else if (r < 140)            v = W1[(r - 130) * HH + j];
    else if (r == 140) {         // c = relu(Wt4) @ Wt3
        float acc = 0.f;
#pragma unroll 8
        for (int h = 0; h < HH; ++h) {
            float t = Wt4[h];
            t = t > 0.f ? t : 0.f;
            acc += t * Wt3[h * HH + j];
        }
        v = acc;
    }                            // rows 141-143: 0
    g_B[r * HH + j] = v;
    if (r == 0) g_bsum[j] = b0[j] + b1[j] + b2[j];
}

// ------------------------------------------------- fp32 -> fp16 feature
__global__ void convert_kernel(const float* __restrict__ f) {
    int i = blockIdx.x * 256 + threadIdx.x;        // one float4 per thread
    float4 v = ((const float4*)f)[i];
    __half2 h0 = __float22half2_rn(make_float2(v.x, v.y));
    __half2 h1 = __float22half2_rn(make_float2(v.z, v.w));
    uint2 o;
    o.x = *(unsigned*)&h0;
    o.y = *(unsigned*)&h1;
    ((uint2*)g_feat)[i] = o;
}

// ------------------------------------------------- gather: 1 warp / node
__global__ void __launch_bounds__(256, 3)
gather_kernel(const float* __restrict__ x,  const float* __restrict__ label,
              const float* __restrict__ w,  const float* __restrict__ et,
              const int*   __restrict__ src) {
    __shared__ float2 meta[8][DD];
    const int wp = threadIdx.x >> 5, lane = threadIdx.x & 31;
    const int n  = blockIdx.x * 8 + wp;            // 3750 * 8 == 30000

    const int base = n * DD + lane;
    int   s_l = src[base];
    float e_l = ((const float2*)et)[base].x;       // et[...,0]
    float S   = w[base] * e_l;
#pragma unroll
    for (int o = 16; o; o >>= 1) S += __shfl_xor_sync(0xffffffffu, S, o);
    meta[wp][lane] = make_float2(e_l, __int_as_float(s_l));
    __syncwarp();

    const uint2* fp = (const uint2*)g_feat;        // 32 uint2 per row (256B)
    float2 a0 = make_float2(0.f, 0.f), a1 = make_float2(0.f, 0.f);
#pragma unroll
    for (int d = 0; d < DD; ++d) {
        float2 me = meta[wp][d];
        int   s = __float_as_int(me.y);
        float e = me.x;
        uint2 q = __ldg(fp + s * (HH / 4) + lane);
        float2 f0 = __half22float2(*(__half2*)&q.x);
        float2 f1 = __half22float2(*(__half2*)&q.y);
        a0.x += f0.x * e; a0.y += f0.y * e;
        a1.x += f1.x * e; a1.y += f1.y * e;
    }

    float* Ar = g_A + n * AP;
    ((float4*)Ar)[lane] = make_float4(a0.x, a0.y, a1.x, a1.y);
    if (lane == 0) Ar[140] = S;
    if (lane < 2)  Ar[128 + lane] = x[n * 2 + lane];
    if (lane < KD) Ar[130 + lane] = label[n * KD + lane];
}

// ------------------------------------------------- GEMM: relu(A[128xK] @ B[Kx128] + bsum)
// 256 threads, thread tile 8m x 8j, K chunks of 48, k-groups of 4.
// Per 4k per thread: 8 LDS.128 (B) + 8 LDS.128 (A) + 128 FFMA2.
__global__ void __launch_bounds__(256, 2)
gemm_kernel(float* __restrict__ out) {
    extern __shared__ float smem[];
    float* As = smem;                   // [128 m][52], k-contiguous
    float* Bs = smem + 128 * ASP;       // [48 k][128 j]

    const int tid = threadIdx.x;
    const int jb  = (tid & 15) * 8;
    const int mb  = (tid >> 4) * 8;
    const int n0  = blockIdx.x * 128;

    ull acc[8][4];
    {
        union { float4 f; ull v[2]; } i0, i1;
        i0.f = *(const float4*)(g_bsum + jb);
        i1.f = *(const float4*)(g_bsum + jb + 4);
#pragma unroll
        for (int i = 0; i < 8; ++i) {
            acc[i][0] = i0.v[0]; acc[i][1] = i0.v[1];
            acc[i][2] = i1.v[0]; acc[i][3] = i1.v[1];
        }
    }

    for (int c = 0; c < KTOT / KC; ++c) {
        // stage As: 128 rows x 48 floats = 1536 float4
#pragma unroll
        for (int t = 0; t < 6; ++t) {
            int i   = t * 256 + tid;
            int row = i / 12, q = i % 12;
            float4 v = __ldg((const float4*)(g_A + (size_t)(n0 + row) * AP + c * KC) + q);
            *(float4*)(As + row * ASP + q * 4) = v;
        }
        // stage Bs: 48 x 128 = 1536 float4
#pragma unroll
        for (int t = 0; t < 6; ++t) {
            int i = t * 256 + tid;
            ((float4*)Bs)[i] = __ldg((const float4*)g_B + c * (KC * HH / 4) + i);
        }
        __syncthreads();

#pragma unroll
        for (int kg = 0; kg < KC / 4; ++kg) {
            const int k0 = kg * 4;
            union { float4 f; ull v[2]; } bv[8];
#pragma unroll
            for (int kk = 0; kk < 4; ++kk) {
                bv[2 * kk].f     = *(const float4*)(Bs + (k0 + kk) * HH + jb);
                bv[2 * kk + 1].f = *(const float4*)(Bs + (k0 + kk) * HH + jb + 4);
            }
#pragma unroll
            for (int m = 0; m < 8; ++m) {
                float4 av = *(const float4*)(As + (mb + m) * ASP + k0);  // 4 k-values
                ull a0 = pack2(av.x, av.x);
                ull a1 = pack2(av.y, av.y);
                ull a2 = pack2(av.z, av.z);
                ull a3 = pack2(av.w, av.w);
                acc[m][0] = fma2(a0, bv[0].v[0], acc[m][0]);
                acc[m][1] = fma2(a0, bv[0].v[1], acc[m][1]);
                acc[m][2] = fma2(a0, bv[1].v[0], acc[m][2]);
                acc[m][3] = fma2(a0, bv[1].v[1], acc[m][3]);
                acc[m][0] = fma2(a1, bv[2].v[0], acc[m][0]);
                acc[m][1] = fma2(a1, bv[2].v[1], acc[m][1]);
                acc[m][2] = fma2(a1, bv[3].v[0], acc[m][2]);
                acc[m][3] = fma2(a1, bv[3].v[1], acc[m][3]);
                acc[m][0] = fma2(a2, bv[4].v[0], acc[m][0]);
                acc[m][1] = fma2(a2, bv[4].v[1], acc[m][1]);
                acc[m][2] = fma2(a2, bv[5].v[0], acc[m][2]);
                acc[m][3] = fma2(a2, bv[5].v[1], acc[m][3]);
                acc[m][0] = fma2(a3, bv[6].v[0], acc[m][0]);
                acc[m][1] = fma2(a3, bv[6].v[1], acc[m][1]);
                acc[m][2] = fma2(a3, bv[7].v[0], acc[m][2]);
                acc[m][3] = fma2(a3, bv[7].v[1], acc[m][3]);
            }
        }
        __syncthreads();
    }

#pragma unroll
    for (int i = 0; i < 8; ++i) {
        int n = n0 + mb + i;
        if (n < NN) {
            float2 q0 = unpk(acc[i][0]), q1 = unpk(acc[i][1]);
            float2 q2 = unpk(acc[i][2]), q3 = unpk(acc[i][3]);
            float4 r0, r1;
            r0.x = fmaxf(q0.x, 0.f); r0.y = fmaxf(q0.y, 0.f);
            r0.z = fmaxf(q1.x, 0.f); r0.w = fmaxf(q1.y, 0.f);
            r1.x = fmaxf(q2.x, 0.f); r1.y = fmaxf(q2.y, 0.f);
            r1.z = fmaxf(q3.x, 0.f); r1.w = fmaxf(q3.y, 0.f);
            ((float4*)(out + n * HH + jb))[0] = r0;
            ((float4*)(out + n * HH + jb))[1] = r1;
        }
    }
}

// ------------------------------------------------- launch
extern "C" void kernel_launch(void* const* d_in, const int* in_sizes, int n_in,
                              void* d_out, int out_size) {
    const float* feature = (const float*)d_in[0];
    const float* x       = (const float*)d_in[1];
    const float* label   = (const float*)d_in[2];
    const float* w       = (const float*)d_in[3];
    const float* et      = (const float*)d_in[4];
    const int*   src     = (const int*)  d_in[5];
    const float* W0      = (const float*)d_in[6];
    const float* b0      = (const float*)d_in[7];
    const float* W1      = (const float*)d_in[8];
    const float* b1      = (const float*)d_in[9];
    const float* W2      = (const float*)d_in[10];
    const float* b2      = (const float*)d_in[11];
    const float* Wt3     = (const float*)d_in[12];
    const float* Wt4     = (const float*)d_in[13];
    float* out = (float*)d_out;

    cudaFuncSetAttribute(gemm_kernel, cudaFuncAttributeMaxDynamicSharedMemorySize,
                         GEMM_SMEM);

    prep_kernel<<<KTOT, HH>>>(W0, b0, W1, b1, W2, b2, Wt3, Wt4);
    convert_kernel<<<(NN * HH / 4) / 256, 256>>>(feature);     // 3750 blocks
    gather_kernel<<<NN / 8, 256>>>(x, label, w, et, src);      // 3750 blocks
    gemm_kernel<<<NPAD / 128, 256, GEMM_SMEM>>>(out);          // 235 blocks
}

// round 12
// speedup vs baseline: 2.1541x; 1.6795x over previous
#include <cuda_runtime.h>
#include <cuda_fp16.h>
#include <cstdint>

#define NN    30000
#define DD    32
#define HH    128
#define KD    10
#define NPAD  30080          // 235 * 128
#define KPAD  144            // 142 used + 2 zero
#define SP    152            // smem k-pitch in halves (304 B, ldmatrix conflict-free)
#define GEMM_SMEM (2 * 128 * SP * 2)   // 77824 B

__device__ __half g_feat[NN * HH];          // fp16 feature cache
__device__ __half g_Ah[NPAD * KPAD];        // A fp16 row-major (zero-init)
__device__ __half g_Bth[128 * KPAD];        // B^T fp16 [n][k] (zero-init)

// ------------------------------------------------- prep: build B^T fp16
// 142 blocks x 128 threads; block r = K-row, thread j = output col n.
__global__ void prep_kernel(const float* __restrict__ W0, const float* __restrict__ b0,
                            const float* __restrict__ W1, const float* __restrict__ b1,
                            const float* __restrict__ W2, const float* __restrict__ b2,
                            const float* __restrict__ Wt3, const float* __restrict__ Wt4) {
    int r = blockIdx.x, j = threadIdx.x;
    float v;
    if (r < 128)        v = W2[r * HH + j];
    else if (r < 130)   v = W0[(r - 128) * HH + j];
    else if (r < 140)   v = W1[(r - 130) * HH + j];
    else if (r == 140) {                     // c = relu(Wt4) @ Wt3
        float acc = 0.f;
#pragma unroll 8
        for (int h = 0; h < HH; ++h) {
            float t = Wt4[h];
            t = t > 0.f ? t : 0.f;
            acc += t * Wt3[h * HH + j];
        }
        v = acc;
    } else              v = b0[j] + b1[j] + b2[j];   // r == 141: bias row
    g_Bth[j * KPAD + r] = __float2half(v);
}

// ------------------------------------------------- fp32 -> fp16 feature
__global__ void convert_kernel(const float* __restrict__ f) {
    int i = blockIdx.x * 256 + threadIdx.x;
    float4 v = ((const float4*)f)[i];
    __half2 h0 = __float22half2_rn(make_float2(v.x, v.y));
    __half2 h1 = __float22half2_rn(make_float2(v.z, v.w));
    uint2 o;
    o.x = *(unsigned*)&h0;
    o.y = *(unsigned*)&h1;
    ((uint2*)g_feat)[i] = o;
}

// ------------------------------------------------- gather: 1 warp / node
__global__ void __launch_bounds__(256, 3)
gather_kernel(const float* __restrict__ x,  const float* __restrict__ label,
              const float* __restrict__ w,  const float* __restrict__ et,
              const int*   __restrict__ src) {
    __shared__ float2 meta[8][DD];
    const int wp = threadIdx.x >> 5, lane = threadIdx.x & 31;
    const int n  = blockIdx.x * 8 + wp;            // 3750 * 8 == 30000

    const int base = n * DD + lane;
    int   s_l = src[base];
    float e_l = ((const float2*)et)[base].x;
    float S   = w[base] * e_l;
#pragma unroll
    for (int o = 16; o; o >>= 1) S += __shfl_xor_sync(0xffffffffu, S, o);
    meta[wp][lane] = make_float2(e_l, __int_as_float(s_l));
    __syncwarp();

    const uint2* fp = (const uint2*)g_feat;
    float2 a0 = make_float2(0.f, 0.f), a1 = make_float2(0.f, 0.f);
#pragma unroll
    for (int d = 0; d < DD; ++d) {
        float2 me = meta[wp][d];
        int   s = __float_as_int(me.y);
        float e = me.x;
        uint2 q = __ldg(fp + s * (HH / 4) + lane);
        float2 f0 = __half22float2(*(__half2*)&q.x);
        float2 f1 = __half22float2(*(__half2*)&q.y);
        a0.x += f0.x * e; a0.y += f0.y * e;
        a1.x += f1.x * e; a1.y += f1.y * e;
    }

    __half* Ar = g_Ah + (size_t)n * KPAD;
    {
        __half2 h0 = __float22half2_rn(a0);
        __half2 h1 = __float22half2_rn(a1);
        uint2 o; o.x = *(unsigned*)&h0; o.y = *(unsigned*)&h1;
        *(uint2*)(Ar + lane * 4) = o;              // k = 4*lane .. 4*lane+3
    }
    float ev;
    if (lane < 2)        ev = x[n * 2 + lane];
    else if (lane < 12)  ev = label[n * KD + lane - 2];
    else if (lane == 12) ev = S;
    else                 ev = 1.0f;
    if (lane < 14)
        Ar[128 + lane] = __float2half(ev);         // k = 128..141
}

// ------------------------------------------------- HMMA GEMM: 128x128 tile / CTA
__device__ __forceinline__ uint32_t s2u(const void* p) {
    uint32_t a;
    asm("{ .reg .u64 t; cvta.to.shared.u64 t, %1; cvt.u32.u64 %0, t; }" : "=r"(a) : "l"(p));
    return a;
}

__global__ void __launch_bounds__(256, 2)
gemm_kernel(float* __restrict__ out) {
    extern __shared__ __half sm[];
    __half* smA = sm;                 // [128 m][SP]
    __half* smB = sm + 128 * SP;      // [128 n][SP]

    const int tid  = threadIdx.x;
    const int wid  = tid >> 5, lane = tid & 31;
    const int n0   = blockIdx.x * 128;

    // stage A tile + B tile: 2304 float4 each (9 per thread)
    {
        const float4* sAg = (const float4*)(g_Ah + (size_t)n0 * KPAD);
        const float4* sBg = (const float4*)g_Bth;
#pragma unroll
        for (int t = 0; t < 9; ++t) {
            int i = t * 256 + tid;
            int row = i / 18, q = i % 18;          // 18 float4 per 144-half row
            *(float4*)(smA + row * SP + q * 8) = __ldg(sAg + i);
            *(float4*)(smB + row * SP + q * 8) = __ldg(sBg + i);
        }
    }
    __syncthreads();

    // warp grid: 4 (m) x 2 (n); warp tile 32m x 64n
    const int wm = (wid >> 1) * 32;
    const int wn = (wid & 1) * 64;

    // ldmatrix lane address bases (halves -> bytes)
    const uint32_t smA_u = s2u(smA), smB_u = s2u(smB);
    // A x4: lane -> row (l&15), k-offset (l>>4)*8
    const uint32_t abase = smA_u + (uint32_t)(wm + (lane & 15)) * (SP * 2) + (lane >> 4) * 16;
    // B x4 (2 n-tiles): lane -> n-row (l&7) + ((l>>4)&1)*8, k-offset ((l>>3)&1)*8
    const uint32_t bbase = smB_u + (uint32_t)(wn + (lane & 7) + ((lane >> 4) << 3)) * (SP * 2)
                                 + ((lane >> 3) & 1) * 16;

    float c[2][8][4];
#pragma unroll
    for (int mt = 0; mt < 2; ++mt)
#pragma unroll
        for (int nt = 0; nt < 8; ++nt)
#pragma unroll
            for (int q = 0; q < 4; ++q) c[mt][nt][q] = 0.f;

#pragma unroll
    for (int ks = 0; ks < 9; ++ks) {
        const uint32_t kb = ks * 32;               // k0*2 bytes
        uint32_t a[2][4];
#pragma unroll
        for (int mt = 0; mt < 2; ++mt)
            asm volatile("ldmatrix.sync.aligned.m8n8.x4.shared.b16 {%0,%1,%2,%3}, [%4];"
                         : "=r"(a[mt][0]), "=r"(a[mt][1]), "=r"(a[mt][2]), "=r"(a[mt][3])
                         : "r"(abase + mt * 16 * (SP * 2) + kb));
#pragma unroll
        for (int ntp = 0; ntp < 4; ++ntp) {
            uint32_t b0, b1, b2, b3;               // b0,b1: nt=2*ntp; b2,b3: nt=2*ntp+1
            asm volatile("ldmatrix.sync.aligned.m8n8.x4.shared.b16 {%0,%1,%2,%3}, [%4];"
                         : "=r"(b0), "=r"(b1), "=r"(b2), "=r"(b3)
                         : "r"(bbase + ntp * 16 * (SP * 2) + kb));
#pragma unroll
            for (int mt = 0; mt < 2; ++mt) {
                asm volatile(
                    "mma.sync.aligned.m16n8k16.row.col.f32.f16.f16.f32 "
                    "{%0,%1,%2,%3}, {%4,%5,%6,%7}, {%8,%9}, {%0,%1,%2,%3};"
                    : "+f"(c[mt][2 * ntp][0]), "+f"(c[mt][2 * ntp][1]),
                      "+f"(c[mt][2 * ntp][2]), "+f"(c[mt][2 * ntp][3])
                    : "r"(a[mt][0]), "r"(a[mt][1]), "r"(a[mt][2]), "r"(a[mt][3]),
                      "r"(b0), "r"(b1));
                asm volatile(
                    "mma.sync.aligned.m16n8k16.row.col.f32.f16.f16.f32 "
                    "{%0,%1,%2,%3}, {%4,%5,%6,%7}, {%8,%9}, {%0,%1,%2,%3};"
                    : "+f"(c[mt][2 * ntp + 1][0]), "+f"(c[mt][2 * ntp + 1][1]),
                      "+f"(c[mt][2 * ntp + 1][2]), "+f"(c[mt][2 * ntp + 1][3])
                    : "r"(a[mt][0]), "r"(a[mt][1]), "r"(a[mt][2]), "r"(a[mt][3]),
                      "r"(b2), "r"(b3));
            }
        }
    }

    // epilogue: relu + store.  c frag: rows (lane>>2), (lane>>2)+8; cols (lane&3)*2,+1
#pragma unroll
    for (int mt = 0; mt < 2; ++mt) {
        const int row0 = n0 + wm + mt * 16 + (lane >> 2);
#pragma unroll
        for (int nt = 0; nt < 8; ++nt) {
            const int col = wn + nt * 8 + (lane & 3) * 2;
            if (row0 < NN) {
                float2 v;
                v.x = fmaxf(c[mt][nt][0], 0.f);
                v.y = fmaxf(c[mt][nt][1], 0.f);
                *(float2*)(out + (size_t)row0 * HH + col) = v;
            }
            if (row0 + 8 < NN) {
                float2 v;
                v.x = fmaxf(c[mt][nt][2], 0.f);
                v.y = fmaxf(c[mt][nt][3], 0.f);
                *(float2*)(out + (size_t)(row0 + 8) * HH + col) = v;
            }
        }
    }
}

// ------------------------------------------------- launch
extern "C" void kernel_launch(void* const* d_in, const int* in_sizes, int n_in,
                              void* d_out, int out_size) {
    const float* feature = (const float*)d_in[0];
    const float* x       = (const float*)d_in[1];
    const float* label   = (const float*)d_in[2];
    const float* w       = (const float*)d_in[3];
    const float* et      = (const float*)d_in[4];
    const int*   src     = (const int*)  d_in[5];
    const float* W0      = (const float*)d_in[6];
    const float* b0      = (const float*)d_in[7];
    const float* W1      = (const float*)d_in[8];
    const float* b1      = (const float*)d_in[9];
    const float* W2      = (const float*)d_in[10];
    const float* b2      = (const float*)d_in[11];
    const float* Wt3     = (const float*)d_in[12];
    const float* Wt4     = (const float*)d_in[13];
    float* out = (float*)d_out;

    cudaFuncSetAttribute(gemm_kernel, cudaFuncAttributeMaxDynamicSharedMemorySize,
                         GEMM_SMEM);

    prep_kernel<<<142, HH>>>(W0, b0, W1, b1, W2, b2, Wt3, Wt4);
    convert_kernel<<<(NN * HH / 4) / 256, 256>>>(feature);     // 3750 blocks
    gather_kernel<<<NN / 8, 256>>>(x, label, w, et, src);      // 3750 blocks
    gemm_kernel<<<NPAD / 128, 256, GEMM_SMEM>>>(out);          // 235 blocks
}